// round 6
// baseline (speedup 1.0000x reference)
#include <cuda_runtime.h>

#define NN   50000
#define EE   800000
#define IND  128
#define EMB  64
#define GG   512
#define OUTD 128
#define EPSV 1e-5f

// ---------------- scratch (static device memory; no allocs allowed) --------
__device__ float g_x [NN*EMB];
__device__ float g_t1[NN*EMB];
__device__ float g_t2[NN*EMB];
__device__ float g_h [NN*EMB];
__device__ int   g_deg[NN];
__device__ float g_dinv[NN];
__device__ float g_ew[EE];
__device__ int   g_start[GG+1];

__device__ __forceinline__ float clamp1(float v) {
    return fminf(fmaxf(v, -1.0f), 1.0f);
}

// ---------------- init ------------------------------------------------------
__global__ void init_kernel() {
    int i = blockIdx.x * blockDim.x + threadIdx.x;
    if (i < NN*EMB) { g_t1[i] = 0.f; g_t2[i] = 0.f; }
    if (i < NN) g_deg[i] = 0;
}

// ---------------- graph boundaries (batch is sorted) ------------------------
__global__ void bounds_kernel(const int* __restrict__ batch) {
    int g = blockIdx.x * blockDim.x + threadIdx.x;
    if (g > GG) return;
    // lower_bound: first i with batch[i] >= g
    int lo = 0, hi = NN;
    while (lo < hi) {
        int mid = (lo + hi) >> 1;
        if (batch[mid] < g) lo = mid + 1; else hi = mid;
    }
    g_start[g] = lo;
}

// ---------------- encoder GEMM + hardtanh -----------------------------------
// 16 nodes per block, 256 threads; thread computes 4 (node,feat) outputs.
__global__ __launch_bounds__(256) void enc_kernel(
    const float* __restrict__ feat, const float* __restrict__ Wenc,
    const float* __restrict__ benc)
{
    __shared__ float Ws[IND*EMB];   // 32 KB, [k][f]
    __shared__ float Fs[16*IND];    // 8 KB
    int nb = blockIdx.x * 16;
    int t  = threadIdx.x;

    for (int i = t; i < IND*EMB; i += 256) Ws[i] = Wenc[i];
    for (int i = t; i < 16*IND; i += 256)
        Fs[i] = feat[(nb + i / IND)*IND + (i % IND)];
    __syncthreads();

    int f  = t & 63;
    int ng = t >> 6;   // 0..3
    float a0 = 0.f, a1 = 0.f, a2 = 0.f, a3 = 0.f;
    #pragma unroll 4
    for (int k = 0; k < IND; k++) {
        float w = Ws[k*EMB + f];
        a0 += Fs[(ng     )*IND + k] * w;
        a1 += Fs[(ng +  4)*IND + k] * w;
        a2 += Fs[(ng +  8)*IND + k] * w;
        a3 += Fs[(ng + 12)*IND + k] * w;
    }
    float b = benc[f];
    g_x[(nb + ng     )*EMB + f] = clamp1(a0 + b);
    g_x[(nb + ng +  4)*EMB + f] = clamp1(a1 + b);
    g_x[(nb + ng +  8)*EMB + f] = clamp1(a2 + b);
    g_x[(nb + ng + 12)*EMB + f] = clamp1(a3 + b);
}

// ---------------- GraphNorm: one block per graph, deterministic -------------
__global__ __launch_bounds__(256) void gn_kernel(
    const float* __restrict__ gw, const float* __restrict__ gb,
    const float* __restrict__ ms)
{
    __shared__ float red[256];
    __shared__ float smean[EMB];
    __shared__ float sscale[EMB];
    int g = blockIdx.x;
    int s = g_start[g], e = g_start[g+1];
    float cnt = fmaxf((float)(e - s), 1.0f);
    int t  = threadIdx.x;
    int f  = t & 63;
    int ng = t >> 6;

    // pass 1: mean
    float a = 0.f;
    for (int n = s + ng; n < e; n += 4) a += g_x[n*EMB + f];
    red[t] = a;
    __syncthreads();
    if (t < EMB)
        smean[t] = (red[t] + red[t+64] + red[t+128] + red[t+192]) / cnt * ms[t];
    __syncthreads();

    // pass 2: center + variance
    float m = smean[f];
    float v2 = 0.f;
    for (int n = s + ng; n < e; n += 4) {
        float v = g_x[n*EMB + f] - m;
        g_x[n*EMB + f] = v;
        v2 += v * v;
    }
    red[t] = v2;
    __syncthreads();
    if (t < EMB) {
        float var = (red[t] + red[t+64] + red[t+128] + red[t+192]) / cnt;
        sscale[t] = gw[t] / sqrtf(var + EPSV);
    }
    __syncthreads();

    // pass 3: scale + bias
    float sc = sscale[f], bb = gb[f];
    for (int n = s + ng; n < e; n += 4)
        g_x[n*EMB + f] = g_x[n*EMB + f] * sc + bb;
}

// ---------------- degree / dinv / edge weights ------------------------------
__global__ void deg_kernel(const int* __restrict__ ei) {
    int e = blockIdx.x * blockDim.x + threadIdx.x;
    if (e < EE) atomicAdd(&g_deg[ei[e]], 1);
}
__global__ void dinv_kernel() {
    int n = blockIdx.x * blockDim.x + threadIdx.x;
    if (n < NN) {
        int d = g_deg[n];
        g_dinv[n] = d > 0 ? 1.0f / sqrtf((float)d) : 0.f;
    }
}
__global__ void ew_kernel(const int* __restrict__ ei) {
    int e = blockIdx.x * blockDim.x + threadIdx.x;
    if (e < EE) g_ew[e] = -g_dinv[ei[e]] * g_dinv[ei[EE + e]];
}

// ---------------- propagation: one warp per edge ----------------------------
__global__ __launch_bounds__(256) void prop1_kernel(const int* __restrict__ ei) {
    int w = (blockIdx.x * blockDim.x + threadIdx.x) >> 5;
    int lane = threadIdx.x & 31;
    if (w >= EE) return;
    int s = ei[w];
    int d = ei[EE + w];
    float sc = g_ew[w];
    float2 v = ((const float2*)(g_x + (size_t)s*EMB))[lane];
    float* o = g_t1 + (size_t)d*EMB + lane*2;
    atomicAdd(o,     sc * v.x);
    atomicAdd(o + 1, sc * v.y);
}
__global__ __launch_bounds__(256) void prop2_kernel(const int* __restrict__ ei) {
    int w = (blockIdx.x * blockDim.x + threadIdx.x) >> 5;
    int lane = threadIdx.x & 31;
    if (w >= EE) return;
    int s = ei[w];
    int d = ei[EE + w];
    float sc = g_ew[w];
    float2 v = ((const float2*)(g_t1 + (size_t)s*EMB))[lane];
    float* o = g_t2 + (size_t)d*EMB + lane*2;
    atomicAdd(o,     sc * v.x);
    atomicAdd(o + 1, sc * v.y);
}

// ---------------- Cheb combine GEMM + hardtanh -> g_h -----------------------
__global__ __launch_bounds__(256) void cheb_kernel(
    const float* __restrict__ chebW, const float* __restrict__ chebB)
{
    __shared__ float xs [16*EMB];
    __shared__ float t1s[16*EMB];
    __shared__ float t2s[16*EMB];
    int nb = blockIdx.x * 16;
    int t  = threadIdx.x;

    for (int i = t; i < 16*EMB; i += 256) {
        int n = nb + i / EMB;
        int k = i % EMB;
        float xv = g_x[n*EMB + k];
        xs[i]  = xv;
        t1s[i] = g_t1[n*EMB + k];
        t2s[i] = 2.0f * g_t2[n*EMB + k] - xv;   // Tx2
    }
    __syncthreads();

    int f  = t & 63;
    int ng = t >> 6;
    const float* W0 = chebW;
    const float* W1 = chebW + EMB*EMB;
    const float* W2 = chebW + 2*EMB*EMB;

    float a0 = 0.f, a1 = 0.f, a2 = 0.f, a3 = 0.f;
    #pragma unroll 4
    for (int k = 0; k < EMB; k++) {
        float w0 = W0[k*EMB + f];
        float w1 = W1[k*EMB + f];
        float w2 = W2[k*EMB + f];
        a0 += xs[(ng     )*EMB + k]*w0 + t1s[(ng     )*EMB + k]*w1 + t2s[(ng     )*EMB + k]*w2;
        a1 += xs[(ng +  4)*EMB + k]*w0 + t1s[(ng +  4)*EMB + k]*w1 + t2s[(ng +  4)*EMB + k]*w2;
        a2 += xs[(ng +  8)*EMB + k]*w0 + t1s[(ng +  8)*EMB + k]*w1 + t2s[(ng +  8)*EMB + k]*w2;
        a3 += xs[(ng + 12)*EMB + k]*w0 + t1s[(ng + 12)*EMB + k]*w1 + t2s[(ng + 12)*EMB + k]*w2;
    }
    float b = chebB[f];
    g_h[(nb + ng     )*EMB + f] = clamp1(a0 + b);
    g_h[(nb + ng +  4)*EMB + f] = clamp1(a1 + b);
    g_h[(nb + ng +  8)*EMB + f] = clamp1(a2 + b);
    g_h[(nb + ng + 12)*EMB + f] = clamp1(a3 + b);
}

// ---------------- pooling + final linear: one block per graph ---------------
__global__ __launch_bounds__(256) void pool_final_kernel(
    const float* __restrict__ Wout, const float* __restrict__ bout,
    float* __restrict__ out)
{
    __shared__ float rmax[256];
    __shared__ float rmin[256];
    __shared__ float rsq [256];
    __shared__ float ys[OUTD];
    int g = blockIdx.x;
    int s = g_start[g], e = g_start[g+1];
    float cnt = fmaxf((float)(e - s), 1.0f);
    int t  = threadIdx.x;
    int f  = t & 63;
    int ng = t >> 6;

    float mx = -2.f, mn = 2.f, sq = 0.f;
    for (int n = s + ng; n < e; n += 4) {
        float h = g_h[n*EMB + f];
        mx = fmaxf(mx, h);
        mn = fminf(mn, h);
        sq += h * h;
    }
    rmax[t] = mx; rmin[t] = mn; rsq[t] = sq;
    __syncthreads();
    if (t < EMB) {
        float M = fmaxf(fmaxf(rmax[t], rmax[t+64]), fmaxf(rmax[t+128], rmax[t+192]));
        float m = fminf(fminf(rmin[t], rmin[t+64]), fminf(rmin[t+128], rmin[t+192]));
        float q = rsq[t] + rsq[t+64] + rsq[t+128] + rsq[t+192];
        ys[t]       = M - m;
        ys[t + EMB] = sqrtf(q / cnt);
    }
    __syncthreads();

    if (t < OUTD) {
        float acc = 0.f;
        #pragma unroll 4
        for (int j = 0; j < OUTD; j++)
            acc += ys[j] * Wout[j*OUTD + t];
        out[g*OUTD + t] = acc + bout[t];
    }
}

// ---------------- launch ----------------------------------------------------
extern "C" void kernel_launch(void* const* d_in, const int* in_sizes, int n_in,
                              void* d_out, int out_size)
{
    const float* feature = (const float*)d_in[0];
    const float* W_enc   = (const float*)d_in[1];
    const float* b_enc   = (const float*)d_in[2];
    const float* gn_w    = (const float*)d_in[3];
    const float* gn_b    = (const float*)d_in[4];
    const float* gn_ms   = (const float*)d_in[5];
    const float* cheb_W  = (const float*)d_in[6];
    const float* cheb_b  = (const float*)d_in[7];
    const float* W_out   = (const float*)d_in[8];
    const float* b_out   = (const float*)d_in[9];
    const int*   ei      = (const int*)  d_in[10];
    const int*   batch   = (const int*)  d_in[11];
    float* out = (float*)d_out;

    const int threads = 256;
    const int grid_ne = (NN*EMB + threads - 1) / threads;
    const int grid_e  = (EE + threads - 1) / threads;
    const int grid_n  = (NN + threads - 1) / threads;
    const int grid_nodes = (NN + 15) / 16;
    const int grid_prop  = (EE * 32 + threads - 1) / threads;

    init_kernel<<<grid_ne, threads>>>();
    bounds_kernel<<<(GG + 1 + 255)/256, 256>>>(batch);
    enc_kernel<<<grid_nodes, threads>>>(feature, W_enc, b_enc);
    gn_kernel<<<GG, threads>>>(gn_w, gn_b, gn_ms);
    deg_kernel<<<grid_e, threads>>>(ei);
    dinv_kernel<<<grid_n, threads>>>();
    ew_kernel<<<grid_e, threads>>>(ei);
    prop1_kernel<<<grid_prop, threads>>>(ei);
    prop2_kernel<<<grid_prop, threads>>>(ei);
    cheb_kernel<<<grid_nodes, threads>>>(cheb_W, cheb_b);
    pool_final_kernel<<<GG, threads>>>(W_out, b_out, out);
}

// round 7
// speedup vs baseline: 1.0072x; 1.0072x over previous
#include <cuda_runtime.h>

#define NN   50000
#define EE   800000
#define IND  128
#define EMB  64
#define GG   512
#define OUTD 128
#define EPSV 1e-5f

// ---------------- scratch (static device memory; no allocs allowed) --------
__device__ float g_x [NN*EMB];
__device__ float g_t1[NN*EMB];
__device__ float g_t2[NN*EMB];
__device__ float g_h [NN*EMB];
__device__ int   g_deg[NN];
__device__ float g_dinv[NN];
__device__ float g_ew[EE];
__device__ int   g_start[GG+1];

__device__ __forceinline__ float clamp1(float v) {
    return fminf(fmaxf(v, -1.0f), 1.0f);
}

// ---------------- init ------------------------------------------------------
__global__ void init_kernel() {
    int i = blockIdx.x * blockDim.x + threadIdx.x;
    if (i < NN*EMB) { g_t1[i] = 0.f; g_t2[i] = 0.f; }
    if (i < NN) g_deg[i] = 0;
}

// ---------------- graph boundaries (batch is sorted) ------------------------
__global__ void bounds_kernel(const int* __restrict__ batch) {
    int g = blockIdx.x * blockDim.x + threadIdx.x;
    if (g > GG) return;
    // lower_bound: first i with batch[i] >= g
    int lo = 0, hi = NN;
    while (lo < hi) {
        int mid = (lo + hi) >> 1;
        if (batch[mid] < g) lo = mid + 1; else hi = mid;
    }
    g_start[g] = lo;
}

// ---------------- encoder GEMM + hardtanh -----------------------------------
// 16 nodes per block, 256 threads; thread computes 4 (node,feat) outputs.
__global__ __launch_bounds__(256) void enc_kernel(
    const float* __restrict__ feat, const float* __restrict__ Wenc,
    const float* __restrict__ benc)
{
    __shared__ float Ws[IND*EMB];   // 32 KB, [k][f]
    __shared__ float Fs[16*IND];    // 8 KB
    int nb = blockIdx.x * 16;
    int t  = threadIdx.x;

    for (int i = t; i < IND*EMB; i += 256) Ws[i] = Wenc[i];
    for (int i = t; i < 16*IND; i += 256)
        Fs[i] = feat[(nb + i / IND)*IND + (i % IND)];
    __syncthreads();

    int f  = t & 63;
    int ng = t >> 6;   // 0..3
    float a0 = 0.f, a1 = 0.f, a2 = 0.f, a3 = 0.f;
    #pragma unroll 4
    for (int k = 0; k < IND; k++) {
        float w = Ws[k*EMB + f];
        a0 += Fs[(ng     )*IND + k] * w;
        a1 += Fs[(ng +  4)*IND + k] * w;
        a2 += Fs[(ng +  8)*IND + k] * w;
        a3 += Fs[(ng + 12)*IND + k] * w;
    }
    float b = benc[f];
    g_x[(nb + ng     )*EMB + f] = clamp1(a0 + b);
    g_x[(nb + ng +  4)*EMB + f] = clamp1(a1 + b);
    g_x[(nb + ng +  8)*EMB + f] = clamp1(a2 + b);
    g_x[(nb + ng + 12)*EMB + f] = clamp1(a3 + b);
}

// ---------------- GraphNorm: one block per graph, deterministic -------------
__global__ __launch_bounds__(256) void gn_kernel(
    const float* __restrict__ gw, const float* __restrict__ gb,
    const float* __restrict__ ms)
{
    __shared__ float red[256];
    __shared__ float smean[EMB];
    __shared__ float sscale[EMB];
    int g = blockIdx.x;
    int s = g_start[g], e = g_start[g+1];
    float cnt = fmaxf((float)(e - s), 1.0f);
    int t  = threadIdx.x;
    int f  = t & 63;
    int ng = t >> 6;

    // pass 1: mean
    float a = 0.f;
    for (int n = s + ng; n < e; n += 4) a += g_x[n*EMB + f];
    red[t] = a;
    __syncthreads();
    if (t < EMB)
        smean[t] = (red[t] + red[t+64] + red[t+128] + red[t+192]) / cnt * ms[t];
    __syncthreads();

    // pass 2: center + variance
    float m = smean[f];
    float v2 = 0.f;
    for (int n = s + ng; n < e; n += 4) {
        float v = g_x[n*EMB + f] - m;
        g_x[n*EMB + f] = v;
        v2 += v * v;
    }
    red[t] = v2;
    __syncthreads();
    if (t < EMB) {
        float var = (red[t] + red[t+64] + red[t+128] + red[t+192]) / cnt;
        sscale[t] = gw[t] / sqrtf(var + EPSV);
    }
    __syncthreads();

    // pass 3: scale + bias
    float sc = sscale[f], bb = gb[f];
    for (int n = s + ng; n < e; n += 4)
        g_x[n*EMB + f] = g_x[n*EMB + f] * sc + bb;
}

// ---------------- degree / dinv / edge weights ------------------------------
__global__ void deg_kernel(const int* __restrict__ ei) {
    int e = blockIdx.x * blockDim.x + threadIdx.x;
    if (e < EE) atomicAdd(&g_deg[ei[e]], 1);
}
__global__ void dinv_kernel() {
    int n = blockIdx.x * blockDim.x + threadIdx.x;
    if (n < NN) {
        int d = g_deg[n];
        g_dinv[n] = d > 0 ? 1.0f / sqrtf((float)d) : 0.f;
    }
}
__global__ void ew_kernel(const int* __restrict__ ei) {
    int e = blockIdx.x * blockDim.x + threadIdx.x;
    if (e < EE) g_ew[e] = -g_dinv[ei[e]] * g_dinv[ei[EE + e]];
}

// ---------------- propagation: one warp per edge ----------------------------
__global__ __launch_bounds__(256) void prop1_kernel(const int* __restrict__ ei) {
    int w = (blockIdx.x * blockDim.x + threadIdx.x) >> 5;
    int lane = threadIdx.x & 31;
    if (w >= EE) return;
    int s = ei[w];
    int d = ei[EE + w];
    float sc = g_ew[w];
    float2 v = ((const float2*)(g_x + (size_t)s*EMB))[lane];
    float* o = g_t1 + (size_t)d*EMB + lane*2;
    atomicAdd(o,     sc * v.x);
    atomicAdd(o + 1, sc * v.y);
}
__global__ __launch_bounds__(256) void prop2_kernel(const int* __restrict__ ei) {
    int w = (blockIdx.x * blockDim.x + threadIdx.x) >> 5;
    int lane = threadIdx.x & 31;
    if (w >= EE) return;
    int s = ei[w];
    int d = ei[EE + w];
    float sc = g_ew[w];
    float2 v = ((const float2*)(g_t1 + (size_t)s*EMB))[lane];
    float* o = g_t2 + (size_t)d*EMB + lane*2;
    atomicAdd(o,     sc * v.x);
    atomicAdd(o + 1, sc * v.y);
}

// ---------------- Cheb combine GEMM + hardtanh -> g_h -----------------------
__global__ __launch_bounds__(256) void cheb_kernel(
    const float* __restrict__ chebW, const float* __restrict__ chebB)
{
    __shared__ float xs [16*EMB];
    __shared__ float t1s[16*EMB];
    __shared__ float t2s[16*EMB];
    int nb = blockIdx.x * 16;
    int t  = threadIdx.x;

    for (int i = t; i < 16*EMB; i += 256) {
        int n = nb + i / EMB;
        int k = i % EMB;
        float xv = g_x[n*EMB + k];
        xs[i]  = xv;
        t1s[i] = g_t1[n*EMB + k];
        t2s[i] = 2.0f * g_t2[n*EMB + k] - xv;   // Tx2
    }
    __syncthreads();

    int f  = t & 63;
    int ng = t >> 6;
    const float* W0 = chebW;
    const float* W1 = chebW + EMB*EMB;
    const float* W2 = chebW + 2*EMB*EMB;

    float a0 = 0.f, a1 = 0.f, a2 = 0.f, a3 = 0.f;
    #pragma unroll 4
    for (int k = 0; k < EMB; k++) {
        float w0 = W0[k*EMB + f];
        float w1 = W1[k*EMB + f];
        float w2 = W2[k*EMB + f];
        a0 += xs[(ng     )*EMB + k]*w0 + t1s[(ng     )*EMB + k]*w1 + t2s[(ng     )*EMB + k]*w2;
        a1 += xs[(ng +  4)*EMB + k]*w0 + t1s[(ng +  4)*EMB + k]*w1 + t2s[(ng +  4)*EMB + k]*w2;
        a2 += xs[(ng +  8)*EMB + k]*w0 + t1s[(ng +  8)*EMB + k]*w1 + t2s[(ng +  8)*EMB + k]*w2;
        a3 += xs[(ng + 12)*EMB + k]*w0 + t1s[(ng + 12)*EMB + k]*w1 + t2s[(ng + 12)*EMB + k]*w2;
    }
    float b = chebB[f];
    g_h[(nb + ng     )*EMB + f] = clamp1(a0 + b);
    g_h[(nb + ng +  4)*EMB + f] = clamp1(a1 + b);
    g_h[(nb + ng +  8)*EMB + f] = clamp1(a2 + b);
    g_h[(nb + ng + 12)*EMB + f] = clamp1(a3 + b);
}

// ---------------- pooling + final linear: one block per graph ---------------
__global__ __launch_bounds__(256) void pool_final_kernel(
    const float* __restrict__ Wout, const float* __restrict__ bout,
    float* __restrict__ out)
{
    __shared__ float rmax[256];
    __shared__ float rmin[256];
    __shared__ float rsq [256];
    __shared__ float ys[OUTD];
    int g = blockIdx.x;
    int s = g_start[g], e = g_start[g+1];
    float cnt = fmaxf((float)(e - s), 1.0f);
    int t  = threadIdx.x;
    int f  = t & 63;
    int ng = t >> 6;

    float mx = -2.f, mn = 2.f, sq = 0.f;
    for (int n = s + ng; n < e; n += 4) {
        float h = g_h[n*EMB + f];
        mx = fmaxf(mx, h);
        mn = fminf(mn, h);
        sq += h * h;
    }
    rmax[t] = mx; rmin[t] = mn; rsq[t] = sq;
    __syncthreads();
    if (t < EMB) {
        float M = fmaxf(fmaxf(rmax[t], rmax[t+64]), fmaxf(rmax[t+128], rmax[t+192]));
        float m = fminf(fminf(rmin[t], rmin[t+64]), fminf(rmin[t+128], rmin[t+192]));
        float q = rsq[t] + rsq[t+64] + rsq[t+128] + rsq[t+192];
        ys[t]       = M - m;
        ys[t + EMB] = sqrtf(q / cnt);
    }
    __syncthreads();

    if (t < OUTD) {
        float acc = 0.f;
        #pragma unroll 4
        for (int j = 0; j < OUTD; j++)
            acc += ys[j] * Wout[j*OUTD + t];
        out[g*OUTD + t] = acc + bout[t];
    }
}

// ---------------- launch ----------------------------------------------------
extern "C" void kernel_launch(void* const* d_in, const int* in_sizes, int n_in,
                              void* d_out, int out_size)
{
    const float* feature = (const float*)d_in[0];
    const float* W_enc   = (const float*)d_in[1];
    const float* b_enc   = (const float*)d_in[2];
    const float* gn_w    = (const float*)d_in[3];
    const float* gn_b    = (const float*)d_in[4];
    const float* gn_ms   = (const float*)d_in[5];
    const float* cheb_W  = (const float*)d_in[6];
    const float* cheb_b  = (const float*)d_in[7];
    const float* W_out   = (const float*)d_in[8];
    const float* b_out   = (const float*)d_in[9];
    const int*   ei      = (const int*)  d_in[10];
    const int*   batch   = (const int*)  d_in[11];
    float* out = (float*)d_out;

    const int threads = 256;
    const int grid_ne = (NN*EMB + threads - 1) / threads;
    const int grid_e  = (EE + threads - 1) / threads;
    const int grid_n  = (NN + threads - 1) / threads;
    const int grid_nodes = (NN + 15) / 16;
    const int grid_prop  = (EE * 32 + threads - 1) / threads;

    init_kernel<<<grid_ne, threads>>>();
    bounds_kernel<<<(GG + 1 + 255)/256, 256>>>(batch);
    enc_kernel<<<grid_nodes, threads>>>(feature, W_enc, b_enc);
    gn_kernel<<<GG, threads>>>(gn_w, gn_b, gn_ms);
    deg_kernel<<<grid_e, threads>>>(ei);
    dinv_kernel<<<grid_n, threads>>>();
    ew_kernel<<<grid_e, threads>>>(ei);
    prop1_kernel<<<grid_prop, threads>>>(ei);
    prop2_kernel<<<grid_prop, threads>>>(ei);
    cheb_kernel<<<grid_nodes, threads>>>(cheb_W, cheb_b);
    pool_final_kernel<<<GG, threads>>>(W_out, b_out, out);
}

// round 8
// speedup vs baseline: 1.0079x; 1.0007x over previous
#include <cuda_runtime.h>

#define NN   50000
#define EE   800000
#define IND  128
#define EMB  64
#define GG   512
#define OUTD 128
#define EPSV 1e-5f

// ---------------- scratch (static device memory; no allocs allowed) --------
__device__ float g_x [NN*EMB];
__device__ float g_t1[NN*EMB];
__device__ float g_t2[NN*EMB];
__device__ float g_h [NN*EMB];
__device__ int   g_deg[NN];
__device__ float g_dinv[NN];
__device__ float g_ew[EE];
__device__ int   g_start[GG+1];

__device__ __forceinline__ float clamp1(float v) {
    return fminf(fmaxf(v, -1.0f), 1.0f);
}

// ---------------- init ------------------------------------------------------
__global__ void init_kernel() {
    int i = blockIdx.x * blockDim.x + threadIdx.x;
    if (i < NN*EMB) { g_t1[i] = 0.f; g_t2[i] = 0.f; }
    if (i < NN) g_deg[i] = 0;
}

// ---------------- graph boundaries (batch is sorted) ------------------------
__global__ void bounds_kernel(const int* __restrict__ batch) {
    int g = blockIdx.x * blockDim.x + threadIdx.x;
    if (g > GG) return;
    // lower_bound: first i with batch[i] >= g
    int lo = 0, hi = NN;
    while (lo < hi) {
        int mid = (lo + hi) >> 1;
        if (batch[mid] < g) lo = mid + 1; else hi = mid;
    }
    g_start[g] = lo;
}

// ---------------- encoder GEMM + hardtanh -----------------------------------
// 16 nodes per block, 256 threads; thread computes 4 (node,feat) outputs.
__global__ __launch_bounds__(256) void enc_kernel(
    const float* __restrict__ feat, const float* __restrict__ Wenc,
    const float* __restrict__ benc)
{
    __shared__ float Ws[IND*EMB];   // 32 KB, [k][f]
    __shared__ float Fs[16*IND];    // 8 KB
    int nb = blockIdx.x * 16;
    int t  = threadIdx.x;

    for (int i = t; i < IND*EMB; i += 256) Ws[i] = Wenc[i];
    for (int i = t; i < 16*IND; i += 256)
        Fs[i] = feat[(nb + i / IND)*IND + (i % IND)];
    __syncthreads();

    int f  = t & 63;
    int ng = t >> 6;   // 0..3
    float a0 = 0.f, a1 = 0.f, a2 = 0.f, a3 = 0.f;
    #pragma unroll 4
    for (int k = 0; k < IND; k++) {
        float w = Ws[k*EMB + f];
        a0 += Fs[(ng     )*IND + k] * w;
        a1 += Fs[(ng +  4)*IND + k] * w;
        a2 += Fs[(ng +  8)*IND + k] * w;
        a3 += Fs[(ng + 12)*IND + k] * w;
    }
    float b = benc[f];
    g_x[(nb + ng     )*EMB + f] = clamp1(a0 + b);
    g_x[(nb + ng +  4)*EMB + f] = clamp1(a1 + b);
    g_x[(nb + ng +  8)*EMB + f] = clamp1(a2 + b);
    g_x[(nb + ng + 12)*EMB + f] = clamp1(a3 + b);
}

// ---------------- GraphNorm: one block per graph, deterministic -------------
__global__ __launch_bounds__(256) void gn_kernel(
    const float* __restrict__ gw, const float* __restrict__ gb,
    const float* __restrict__ ms)
{
    __shared__ float red[256];
    __shared__ float smean[EMB];
    __shared__ float sscale[EMB];
    int g = blockIdx.x;
    int s = g_start[g], e = g_start[g+1];
    float cnt = fmaxf((float)(e - s), 1.0f);
    int t  = threadIdx.x;
    int f  = t & 63;
    int ng = t >> 6;

    // pass 1: mean
    float a = 0.f;
    for (int n = s + ng; n < e; n += 4) a += g_x[n*EMB + f];
    red[t] = a;
    __syncthreads();
    if (t < EMB)
        smean[t] = (red[t] + red[t+64] + red[t+128] + red[t+192]) / cnt * ms[t];
    __syncthreads();

    // pass 2: center + variance
    float m = smean[f];
    float v2 = 0.f;
    for (int n = s + ng; n < e; n += 4) {
        float v = g_x[n*EMB + f] - m;
        g_x[n*EMB + f] = v;
        v2 += v * v;
    }
    red[t] = v2;
    __syncthreads();
    if (t < EMB) {
        float var = (red[t] + red[t+64] + red[t+128] + red[t+192]) / cnt;
        sscale[t] = gw[t] / sqrtf(var + EPSV);
    }
    __syncthreads();

    // pass 3: scale + bias
    float sc = sscale[f], bb = gb[f];
    for (int n = s + ng; n < e; n += 4)
        g_x[n*EMB + f] = g_x[n*EMB + f] * sc + bb;
}

// ---------------- degree / dinv / edge weights ------------------------------
__global__ void deg_kernel(const int* __restrict__ ei) {
    int e = blockIdx.x * blockDim.x + threadIdx.x;
    if (e < EE) atomicAdd(&g_deg[ei[e]], 1);
}
__global__ void dinv_kernel() {
    int n = blockIdx.x * blockDim.x + threadIdx.x;
    if (n < NN) {
        int d = g_deg[n];
        g_dinv[n] = d > 0 ? 1.0f / sqrtf((float)d) : 0.f;
    }
}
__global__ void ew_kernel(const int* __restrict__ ei) {
    int e = blockIdx.x * blockDim.x + threadIdx.x;
    if (e < EE) g_ew[e] = -g_dinv[ei[e]] * g_dinv[ei[EE + e]];
}

// ---------------- propagation: one warp per edge ----------------------------
__global__ __launch_bounds__(256) void prop1_kernel(const int* __restrict__ ei) {
    int w = (blockIdx.x * blockDim.x + threadIdx.x) >> 5;
    int lane = threadIdx.x & 31;
    if (w >= EE) return;
    int s = ei[w];
    int d = ei[EE + w];
    float sc = g_ew[w];
    float2 v = ((const float2*)(g_x + (size_t)s*EMB))[lane];
    float* o = g_t1 + (size_t)d*EMB + lane*2;
    atomicAdd(o,     sc * v.x);
    atomicAdd(o + 1, sc * v.y);
}
__global__ __launch_bounds__(256) void prop2_kernel(const int* __restrict__ ei) {
    int w = (blockIdx.x * blockDim.x + threadIdx.x) >> 5;
    int lane = threadIdx.x & 31;
    if (w >= EE) return;
    int s = ei[w];
    int d = ei[EE + w];
    float sc = g_ew[w];
    float2 v = ((const float2*)(g_t1 + (size_t)s*EMB))[lane];
    float* o = g_t2 + (size_t)d*EMB + lane*2;
    atomicAdd(o,     sc * v.x);
    atomicAdd(o + 1, sc * v.y);
}

// ---------------- Cheb combine GEMM + hardtanh -> g_h -----------------------
__global__ __launch_bounds__(256) void cheb_kernel(
    const float* __restrict__ chebW, const float* __restrict__ chebB)
{
    __shared__ float xs [16*EMB];
    __shared__ float t1s[16*EMB];
    __shared__ float t2s[16*EMB];
    int nb = blockIdx.x * 16;
    int t  = threadIdx.x;

    for (int i = t; i < 16*EMB; i += 256) {
        int n = nb + i / EMB;
        int k = i % EMB;
        float xv = g_x[n*EMB + k];
        xs[i]  = xv;
        t1s[i] = g_t1[n*EMB + k];
        t2s[i] = 2.0f * g_t2[n*EMB + k] - xv;   // Tx2
    }
    __syncthreads();

    int f  = t & 63;
    int ng = t >> 6;
    const float* W0 = chebW;
    const float* W1 = chebW + EMB*EMB;
    const float* W2 = chebW + 2*EMB*EMB;

    float a0 = 0.f, a1 = 0.f, a2 = 0.f, a3 = 0.f;
    #pragma unroll 4
    for (int k = 0; k < EMB; k++) {
        float w0 = W0[k*EMB + f];
        float w1 = W1[k*EMB + f];
        float w2 = W2[k*EMB + f];
        a0 += xs[(ng     )*EMB + k]*w0 + t1s[(ng     )*EMB + k]*w1 + t2s[(ng     )*EMB + k]*w2;
        a1 += xs[(ng +  4)*EMB + k]*w0 + t1s[(ng +  4)*EMB + k]*w1 + t2s[(ng +  4)*EMB + k]*w2;
        a2 += xs[(ng +  8)*EMB + k]*w0 + t1s[(ng +  8)*EMB + k]*w1 + t2s[(ng +  8)*EMB + k]*w2;
        a3 += xs[(ng + 12)*EMB + k]*w0 + t1s[(ng + 12)*EMB + k]*w1 + t2s[(ng + 12)*EMB + k]*w2;
    }
    float b = chebB[f];
    g_h[(nb + ng     )*EMB + f] = clamp1(a0 + b);
    g_h[(nb + ng +  4)*EMB + f] = clamp1(a1 + b);
    g_h[(nb + ng +  8)*EMB + f] = clamp1(a2 + b);
    g_h[(nb + ng + 12)*EMB + f] = clamp1(a3 + b);
}

// ---------------- pooling + final linear: one block per graph ---------------
__global__ __launch_bounds__(256) void pool_final_kernel(
    const float* __restrict__ Wout, const float* __restrict__ bout,
    float* __restrict__ out)
{
    __shared__ float rmax[256];
    __shared__ float rmin[256];
    __shared__ float rsq [256];
    __shared__ float ys[OUTD];
    int g = blockIdx.x;
    int s = g_start[g], e = g_start[g+1];
    float cnt = fmaxf((float)(e - s), 1.0f);
    int t  = threadIdx.x;
    int f  = t & 63;
    int ng = t >> 6;

    float mx = -2.f, mn = 2.f, sq = 0.f;
    for (int n = s + ng; n < e; n += 4) {
        float h = g_h[n*EMB + f];
        mx = fmaxf(mx, h);
        mn = fminf(mn, h);
        sq += h * h;
    }
    rmax[t] = mx; rmin[t] = mn; rsq[t] = sq;
    __syncthreads();
    if (t < EMB) {
        float M = fmaxf(fmaxf(rmax[t], rmax[t+64]), fmaxf(rmax[t+128], rmax[t+192]));
        float m = fminf(fminf(rmin[t], rmin[t+64]), fminf(rmin[t+128], rmin[t+192]));
        float q = rsq[t] + rsq[t+64] + rsq[t+128] + rsq[t+192];
        ys[t]       = M - m;
        ys[t + EMB] = sqrtf(q / cnt);
    }
    __syncthreads();

    if (t < OUTD) {
        float acc = 0.f;
        #pragma unroll 4
        for (int j = 0; j < OUTD; j++)
            acc += ys[j] * Wout[j*OUTD + t];
        out[g*OUTD + t] = acc + bout[t];
    }
}

// ---------------- launch ----------------------------------------------------
extern "C" void kernel_launch(void* const* d_in, const int* in_sizes, int n_in,
                              void* d_out, int out_size)
{
    const float* feature = (const float*)d_in[0];
    const float* W_enc   = (const float*)d_in[1];
    const float* b_enc   = (const float*)d_in[2];
    const float* gn_w    = (const float*)d_in[3];
    const float* gn_b    = (const float*)d_in[4];
    const float* gn_ms   = (const float*)d_in[5];
    const float* cheb_W  = (const float*)d_in[6];
    const float* cheb_b  = (const float*)d_in[7];
    const float* W_out   = (const float*)d_in[8];
    const float* b_out   = (const float*)d_in[9];
    const int*   ei      = (const int*)  d_in[10];
    const int*   batch   = (const int*)  d_in[11];
    float* out = (float*)d_out;

    const int threads = 256;
    const int grid_ne = (NN*EMB + threads - 1) / threads;
    const int grid_e  = (EE + threads - 1) / threads;
    const int grid_n  = (NN + threads - 1) / threads;
    const int grid_nodes = (NN + 15) / 16;
    const int grid_prop  = (EE * 32 + threads - 1) / threads;

    init_kernel<<<grid_ne, threads>>>();
    bounds_kernel<<<(GG + 1 + 255)/256, 256>>>(batch);
    enc_kernel<<<grid_nodes, threads>>>(feature, W_enc, b_enc);
    gn_kernel<<<GG, threads>>>(gn_w, gn_b, gn_ms);
    deg_kernel<<<grid_e, threads>>>(ei);
    dinv_kernel<<<grid_n, threads>>>();
    ew_kernel<<<grid_e, threads>>>(ei);
    prop1_kernel<<<grid_prop, threads>>>(ei);
    prop2_kernel<<<grid_prop, threads>>>(ei);
    cheb_kernel<<<grid_nodes, threads>>>(cheb_W, cheb_b);
    pool_final_kernel<<<GG, threads>>>(W_out, b_out, out);
}

// round 9
// speedup vs baseline: 1.0082x; 1.0003x over previous
#include <cuda_runtime.h>

#define NN   50000
#define EE   800000
#define IND  128
#define EMB  64
#define GG   512
#define OUTD 128
#define EPSV 1e-5f

// ---------------- scratch (static device memory; no allocs allowed) --------
__device__ float g_x [NN*EMB];
__device__ float g_t1[NN*EMB];
__device__ float g_t2[NN*EMB];
__device__ float g_h [NN*EMB];
__device__ int   g_deg[NN];
__device__ float g_dinv[NN];
__device__ float g_ew[EE];
__device__ int   g_start[GG+1];

__device__ __forceinline__ float clamp1(float v) {
    return fminf(fmaxf(v, -1.0f), 1.0f);
}

// ---------------- init ------------------------------------------------------
__global__ void init_kernel() {
    int i = blockIdx.x * blockDim.x + threadIdx.x;
    if (i < NN*EMB) { g_t1[i] = 0.f; g_t2[i] = 0.f; }
    if (i < NN) g_deg[i] = 0;
}

// ---------------- graph boundaries (batch is sorted) ------------------------
__global__ void bounds_kernel(const int* __restrict__ batch) {
    int g = blockIdx.x * blockDim.x + threadIdx.x;
    if (g > GG) return;
    // lower_bound: first i with batch[i] >= g
    int lo = 0, hi = NN;
    while (lo < hi) {
        int mid = (lo + hi) >> 1;
        if (batch[mid] < g) lo = mid + 1; else hi = mid;
    }
    g_start[g] = lo;
}

// ---------------- encoder GEMM + hardtanh -----------------------------------
// 16 nodes per block, 256 threads; thread computes 4 (node,feat) outputs.
__global__ __launch_bounds__(256) void enc_kernel(
    const float* __restrict__ feat, const float* __restrict__ Wenc,
    const float* __restrict__ benc)
{
    __shared__ float Ws[IND*EMB];   // 32 KB, [k][f]
    __shared__ float Fs[16*IND];    // 8 KB
    int nb = blockIdx.x * 16;
    int t  = threadIdx.x;

    for (int i = t; i < IND*EMB; i += 256) Ws[i] = Wenc[i];
    for (int i = t; i < 16*IND; i += 256)
        Fs[i] = feat[(nb + i / IND)*IND + (i % IND)];
    __syncthreads();

    int f  = t & 63;
    int ng = t >> 6;   // 0..3
    float a0 = 0.f, a1 = 0.f, a2 = 0.f, a3 = 0.f;
    #pragma unroll 4
    for (int k = 0; k < IND; k++) {
        float w = Ws[k*EMB + f];
        a0 += Fs[(ng     )*IND + k] * w;
        a1 += Fs[(ng +  4)*IND + k] * w;
        a2 += Fs[(ng +  8)*IND + k] * w;
        a3 += Fs[(ng + 12)*IND + k] * w;
    }
    float b = benc[f];
    g_x[(nb + ng     )*EMB + f] = clamp1(a0 + b);
    g_x[(nb + ng +  4)*EMB + f] = clamp1(a1 + b);
    g_x[(nb + ng +  8)*EMB + f] = clamp1(a2 + b);
    g_x[(nb + ng + 12)*EMB + f] = clamp1(a3 + b);
}

// ---------------- GraphNorm: one block per graph, deterministic -------------
__global__ __launch_bounds__(256) void gn_kernel(
    const float* __restrict__ gw, const float* __restrict__ gb,
    const float* __restrict__ ms)
{
    __shared__ float red[256];
    __shared__ float smean[EMB];
    __shared__ float sscale[EMB];
    int g = blockIdx.x;
    int s = g_start[g], e = g_start[g+1];
    float cnt = fmaxf((float)(e - s), 1.0f);
    int t  = threadIdx.x;
    int f  = t & 63;
    int ng = t >> 6;

    // pass 1: mean
    float a = 0.f;
    for (int n = s + ng; n < e; n += 4) a += g_x[n*EMB + f];
    red[t] = a;
    __syncthreads();
    if (t < EMB)
        smean[t] = (red[t] + red[t+64] + red[t+128] + red[t+192]) / cnt * ms[t];
    __syncthreads();

    // pass 2: center + variance
    float m = smean[f];
    float v2 = 0.f;
    for (int n = s + ng; n < e; n += 4) {
        float v = g_x[n*EMB + f] - m;
        g_x[n*EMB + f] = v;
        v2 += v * v;
    }
    red[t] = v2;
    __syncthreads();
    if (t < EMB) {
        float var = (red[t] + red[t+64] + red[t+128] + red[t+192]) / cnt;
        sscale[t] = gw[t] / sqrtf(var + EPSV);
    }
    __syncthreads();

    // pass 3: scale + bias
    float sc = sscale[f], bb = gb[f];
    for (int n = s + ng; n < e; n += 4)
        g_x[n*EMB + f] = g_x[n*EMB + f] * sc + bb;
}

// ---------------- degree / dinv / edge weights ------------------------------
__global__ void deg_kernel(const int* __restrict__ ei) {
    int e = blockIdx.x * blockDim.x + threadIdx.x;
    if (e < EE) atomicAdd(&g_deg[ei[e]], 1);
}
__global__ void dinv_kernel() {
    int n = blockIdx.x * blockDim.x + threadIdx.x;
    if (n < NN) {
        int d = g_deg[n];
        g_dinv[n] = d > 0 ? 1.0f / sqrtf((float)d) : 0.f;
    }
}
__global__ void ew_kernel(const int* __restrict__ ei) {
    int e = blockIdx.x * blockDim.x + threadIdx.x;
    if (e < EE) g_ew[e] = -g_dinv[ei[e]] * g_dinv[ei[EE + e]];
}

// ---------------- propagation: one warp per edge ----------------------------
__global__ __launch_bounds__(256) void prop1_kernel(const int* __restrict__ ei) {
    int w = (blockIdx.x * blockDim.x + threadIdx.x) >> 5;
    int lane = threadIdx.x & 31;
    if (w >= EE) return;
    int s = ei[w];
    int d = ei[EE + w];
    float sc = g_ew[w];
    float2 v = ((const float2*)(g_x + (size_t)s*EMB))[lane];
    float* o = g_t1 + (size_t)d*EMB + lane*2;
    atomicAdd(o,     sc * v.x);
    atomicAdd(o + 1, sc * v.y);
}
__global__ __launch_bounds__(256) void prop2_kernel(const int* __restrict__ ei) {
    int w = (blockIdx.x * blockDim.x + threadIdx.x) >> 5;
    int lane = threadIdx.x & 31;
    if (w >= EE) return;
    int s = ei[w];
    int d = ei[EE + w];
    float sc = g_ew[w];
    float2 v = ((const float2*)(g_t1 + (size_t)s*EMB))[lane];
    float* o = g_t2 + (size_t)d*EMB + lane*2;
    atomicAdd(o,     sc * v.x);
    atomicAdd(o + 1, sc * v.y);
}

// ---------------- Cheb combine GEMM + hardtanh -> g_h -----------------------
__global__ __launch_bounds__(256) void cheb_kernel(
    const float* __restrict__ chebW, const float* __restrict__ chebB)
{
    __shared__ float xs [16*EMB];
    __shared__ float t1s[16*EMB];
    __shared__ float t2s[16*EMB];
    int nb = blockIdx.x * 16;
    int t  = threadIdx.x;

    for (int i = t; i < 16*EMB; i += 256) {
        int n = nb + i / EMB;
        int k = i % EMB;
        float xv = g_x[n*EMB + k];
        xs[i]  = xv;
        t1s[i] = g_t1[n*EMB + k];
        t2s[i] = 2.0f * g_t2[n*EMB + k] - xv;   // Tx2
    }
    __syncthreads();

    int f  = t & 63;
    int ng = t >> 6;
    const float* W0 = chebW;
    const float* W1 = chebW + EMB*EMB;
    const float* W2 = chebW + 2*EMB*EMB;

    float a0 = 0.f, a1 = 0.f, a2 = 0.f, a3 = 0.f;
    #pragma unroll 4
    for (int k = 0; k < EMB; k++) {
        float w0 = W0[k*EMB + f];
        float w1 = W1[k*EMB + f];
        float w2 = W2[k*EMB + f];
        a0 += xs[(ng     )*EMB + k]*w0 + t1s[(ng     )*EMB + k]*w1 + t2s[(ng     )*EMB + k]*w2;
        a1 += xs[(ng +  4)*EMB + k]*w0 + t1s[(ng +  4)*EMB + k]*w1 + t2s[(ng +  4)*EMB + k]*w2;
        a2 += xs[(ng +  8)*EMB + k]*w0 + t1s[(ng +  8)*EMB + k]*w1 + t2s[(ng +  8)*EMB + k]*w2;
        a3 += xs[(ng + 12)*EMB + k]*w0 + t1s[(ng + 12)*EMB + k]*w1 + t2s[(ng + 12)*EMB + k]*w2;
    }
    float b = chebB[f];
    g_h[(nb + ng     )*EMB + f] = clamp1(a0 + b);
    g_h[(nb + ng +  4)*EMB + f] = clamp1(a1 + b);
    g_h[(nb + ng +  8)*EMB + f] = clamp1(a2 + b);
    g_h[(nb + ng + 12)*EMB + f] = clamp1(a3 + b);
}

// ---------------- pooling + final linear: one block per graph ---------------
__global__ __launch_bounds__(256) void pool_final_kernel(
    const float* __restrict__ Wout, const float* __restrict__ bout,
    float* __restrict__ out)
{
    __shared__ float rmax[256];
    __shared__ float rmin[256];
    __shared__ float rsq [256];
    __shared__ float ys[OUTD];
    int g = blockIdx.x;
    int s = g_start[g], e = g_start[g+1];
    float cnt = fmaxf((float)(e - s), 1.0f);
    int t  = threadIdx.x;
    int f  = t & 63;
    int ng = t >> 6;

    float mx = -2.f, mn = 2.f, sq = 0.f;
    for (int n = s + ng; n < e; n += 4) {
        float h = g_h[n*EMB + f];
        mx = fmaxf(mx, h);
        mn = fminf(mn, h);
        sq += h * h;
    }
    rmax[t] = mx; rmin[t] = mn; rsq[t] = sq;
    __syncthreads();
    if (t < EMB) {
        float M = fmaxf(fmaxf(rmax[t], rmax[t+64]), fmaxf(rmax[t+128], rmax[t+192]));
        float m = fminf(fminf(rmin[t], rmin[t+64]), fminf(rmin[t+128], rmin[t+192]));
        float q = rsq[t] + rsq[t+64] + rsq[t+128] + rsq[t+192];
        ys[t]       = M - m;
        ys[t + EMB] = sqrtf(q / cnt);
    }
    __syncthreads();

    if (t < OUTD) {
        float acc = 0.f;
        #pragma unroll 4
        for (int j = 0; j < OUTD; j++)
            acc += ys[j] * Wout[j*OUTD + t];
        out[g*OUTD + t] = acc + bout[t];
    }
}

// ---------------- launch ----------------------------------------------------
extern "C" void kernel_launch(void* const* d_in, const int* in_sizes, int n_in,
                              void* d_out, int out_size)
{
    const float* feature = (const float*)d_in[0];
    const float* W_enc   = (const float*)d_in[1];
    const float* b_enc   = (const float*)d_in[2];
    const float* gn_w    = (const float*)d_in[3];
    const float* gn_b    = (const float*)d_in[4];
    const float* gn_ms   = (const float*)d_in[5];
    const float* cheb_W  = (const float*)d_in[6];
    const float* cheb_b  = (const float*)d_in[7];
    const float* W_out   = (const float*)d_in[8];
    const float* b_out   = (const float*)d_in[9];
    const int*   ei      = (const int*)  d_in[10];
    const int*   batch   = (const int*)  d_in[11];
    float* out = (float*)d_out;

    const int threads = 256;
    const int grid_ne = (NN*EMB + threads - 1) / threads;
    const int grid_e  = (EE + threads - 1) / threads;
    const int grid_n  = (NN + threads - 1) / threads;
    const int grid_nodes = (NN + 15) / 16;
    const int grid_prop  = (EE * 32 + threads - 1) / threads;

    init_kernel<<<grid_ne, threads>>>();
    bounds_kernel<<<(GG + 1 + 255)/256, 256>>>(batch);
    enc_kernel<<<grid_nodes, threads>>>(feature, W_enc, b_enc);
    gn_kernel<<<GG, threads>>>(gn_w, gn_b, gn_ms);
    deg_kernel<<<grid_e, threads>>>(ei);
    dinv_kernel<<<grid_n, threads>>>();
    ew_kernel<<<grid_e, threads>>>(ei);
    prop1_kernel<<<grid_prop, threads>>>(ei);
    prop2_kernel<<<grid_prop, threads>>>(ei);
    cheb_kernel<<<grid_nodes, threads>>>(cheb_W, cheb_b);
    pool_final_kernel<<<GG, threads>>>(W_out, b_out, out);
}